// round 2
// baseline (speedup 1.0000x reference)
#include <cuda_runtime.h>
#include <cuda_bf16.h>
#include <cstdint>

#define CEPS 1e-8f

// scratch (N<=8192, S<=4096 for this problem)
static __device__ float g_norm_emb[16384]; // speech rows [0,N), face rows [N,2N)
static __device__ float g_norm_mem[8192];  // svm rows [0,S), fkm rows [S,2S)
static __device__ float g_lse[16384];      // speech rows [0,N), face rows [N,2N)

__device__ __forceinline__ unsigned pk(float a, float b){
    __nv_bfloat162 h = __floats2bfloat162_rn(a, b);
    return *reinterpret_cast<unsigned*>(&h);
}
// split f32x4 -> (hi bf16x4, lo bf16x4) packed as uint2 each
__device__ __forceinline__ void split4(float4 v, uint2 &hi, uint2 &lo){
    __nv_bfloat16 hx = __float2bfloat16(v.x), hy = __float2bfloat16(v.y);
    __nv_bfloat16 hz = __float2bfloat16(v.z), hw = __float2bfloat16(v.w);
    float lx = v.x - __bfloat162float(hx), ly = v.y - __bfloat162float(hy);
    float lz = v.z - __bfloat162float(hz), lw = v.w - __bfloat162float(hw);
    __nv_bfloat162 h0 = __halves2bfloat162(hx, hy), h1 = __halves2bfloat162(hz, hw);
    hi = make_uint2(*reinterpret_cast<unsigned*>(&h0), *reinterpret_cast<unsigned*>(&h1));
    lo = make_uint2(pk(lx, ly), pk(lz, lw));
}

__device__ __forceinline__ void ldsm4(unsigned r[4], const void* p){
    uint32_t a = (uint32_t)__cvta_generic_to_shared(p);
    asm volatile("ldmatrix.sync.aligned.m8n8.x4.shared.b16 {%0,%1,%2,%3}, [%4];\n"
        : "=r"(r[0]), "=r"(r[1]), "=r"(r[2]), "=r"(r[3]) : "r"(a));
}
__device__ __forceinline__ void ldsm4t(unsigned r[4], const void* p){
    uint32_t a = (uint32_t)__cvta_generic_to_shared(p);
    asm volatile("ldmatrix.sync.aligned.m8n8.x4.trans.shared.b16 {%0,%1,%2,%3}, [%4];\n"
        : "=r"(r[0]), "=r"(r[1]), "=r"(r[2]), "=r"(r[3]) : "r"(a));
}
__device__ __forceinline__ void mma16816(float c[4], const unsigned a[4], unsigned b0, unsigned b1){
    asm volatile("mma.sync.aligned.m16n8k16.row.col.f32.bf16.bf16.f32 "
        "{%0,%1,%2,%3}, {%4,%5,%6,%7}, {%8,%9}, {%0,%1,%2,%3};\n"
        : "+f"(c[0]), "+f"(c[1]), "+f"(c[2]), "+f"(c[3])
        : "r"(a[0]), "r"(a[1]), "r"(a[2]), "r"(a[3]), "r"(b0), "r"(b1));
}

// ---------------- row norms: one warp per row of 256 f32 ----------------
__global__ void norms_kernel(const float* __restrict__ face, const float* __restrict__ speech,
                             const float* __restrict__ svm, const float* __restrict__ fkm,
                             int N, int S){
    int warp = threadIdx.x >> 5, lane = threadIdx.x & 31;
    int rid = blockIdx.x * 8 + warp;
    int total = 2*N + 2*S;
    if (rid >= total) return;
    const float* src; float* dst;
    if (rid < N)            { src = speech + (long)rid * 256;         dst = g_norm_emb + rid; }
    else if (rid < 2*N)     { src = face   + (long)(rid - N) * 256;   dst = g_norm_emb + rid; }
    else if (rid < 2*N + S) { src = svm    + (long)(rid - 2*N) * 256; dst = g_norm_mem + (rid - 2*N); }
    else                    { src = fkm    + (long)(rid - 2*N - S) * 256; dst = g_norm_mem + (rid - 2*N); }
    const float4* p = reinterpret_cast<const float4*>(src);
    float4 v0 = p[lane], v1 = p[lane + 32];
    float s = v0.x*v0.x + v0.y*v0.y + v0.z*v0.z + v0.w*v0.w
            + v1.x*v1.x + v1.y*v1.y + v1.z*v1.z + v1.w*v1.w;
    #pragma unroll
    for (int o = 16; o; o >>= 1) s += __shfl_xor_sync(0xffffffffu, s, o);
    if (lane == 0) *dst = sqrtf(s);
}

// ---------------- logits GEMM: cos = (A@B^T)/max(|a||b|,eps) ----------------
// 3xbf16 (hi/lo split) for near-fp32 precision.
// BM=128, BN=128, BK=32, 256 threads, 8 warps as 4(m) x 2(n), warp tile 32x64.
__global__ __launch_bounds__(256) void logits_kernel(
    const float* __restrict__ A, const float* __restrict__ B,
    float* __restrict__ out, int S, int naoff, int nboff)
{
    __shared__ __align__(16) __nv_bfloat16 Ah[128][40];
    __shared__ __align__(16) __nv_bfloat16 Al[128][40];
    __shared__ __align__(16) __nv_bfloat16 Bh[128][40];
    __shared__ __align__(16) __nv_bfloat16 Bl[128][40];
    const int tid = threadIdx.x;
    const int warp = tid >> 5, lane = tid & 31;
    const int wm = warp >> 1, wn = warp & 1;
    const long bm = blockIdx.y, bn = blockIdx.x;
    const float* Ab = A + bm * 128 * 256;
    const float* Bb = B + bn * 128 * 256;

    float acc[2][8][4];
    #pragma unroll
    for (int i = 0; i < 2; i++)
        #pragma unroll
        for (int j = 0; j < 8; j++)
            #pragma unroll
            for (int k = 0; k < 4; k++) acc[i][j][k] = 0.f;

    for (int kb = 0; kb < 8; ++kb) {
        #pragma unroll
        for (int j = 0; j < 4; ++j) {
            int idx = tid + j * 256;
            int r = idx >> 3, c4 = idx & 7;
            uint2 hi, lo;
            float4 v = *reinterpret_cast<const float4*>(Ab + r * 256 + kb * 32 + c4 * 4);
            split4(v, hi, lo);
            *reinterpret_cast<uint2*>(&Ah[r][c4 * 4]) = hi;
            *reinterpret_cast<uint2*>(&Al[r][c4 * 4]) = lo;
            float4 w = *reinterpret_cast<const float4*>(Bb + r * 256 + kb * 32 + c4 * 4);
            split4(w, hi, lo);
            *reinterpret_cast<uint2*>(&Bh[r][c4 * 4]) = hi;
            *reinterpret_cast<uint2*>(&Bl[r][c4 * 4]) = lo;
        }
        __syncthreads();
        #pragma unroll
        for (int kk = 0; kk < 2; ++kk) {
            unsigned ah[2][4], al[2][4], bh[4][4], bl[4][4];
            #pragma unroll
            for (int mt = 0; mt < 2; ++mt) {
                int r = wm * 32 + mt * 16 + (lane & 15);
                int c = kk * 16 + ((lane >> 4) << 3);
                ldsm4(ah[mt], &Ah[r][c]);
                ldsm4(al[mt], &Al[r][c]);
            }
            #pragma unroll
            for (int np = 0; np < 4; ++np) {
                int g = lane >> 3;
                int r = wn * 64 + np * 16 + ((g >> 1) << 3) + (lane & 7);
                int c = kk * 16 + ((g & 1) << 3);
                ldsm4(bh[np], &Bh[r][c]);
                ldsm4(bl[np], &Bl[r][c]);
            }
            #pragma unroll
            for (int mt = 0; mt < 2; ++mt)
                #pragma unroll
                for (int nt = 0; nt < 8; ++nt) {
                    unsigned h0 = bh[nt >> 1][(nt & 1) * 2], h1 = bh[nt >> 1][(nt & 1) * 2 + 1];
                    unsigned l0 = bl[nt >> 1][(nt & 1) * 2], l1 = bl[nt >> 1][(nt & 1) * 2 + 1];
                    mma16816(acc[mt][nt], ah[mt], h0, h1);   // hi*hi
                    mma16816(acc[mt][nt], ah[mt], l0, l1);   // hi*lo
                    mma16816(acc[mt][nt], al[mt], h0, h1);   // lo*hi
                }
        }
        __syncthreads();
    }

    #pragma unroll
    for (int mt = 0; mt < 2; ++mt) {
        int r = (int)(bm * 128) + wm * 32 + mt * 16 + (lane >> 2);
        float na0 = g_norm_emb[naoff + r];
        float na1 = g_norm_emb[naoff + r + 8];
        #pragma unroll
        for (int nt = 0; nt < 8; ++nt) {
            int c = (int)(bn * 128) + wn * 64 + nt * 8 + (lane & 3) * 2;
            float nb0 = g_norm_mem[nboff + c];
            float nb1 = g_norm_mem[nboff + c + 1];
            *reinterpret_cast<float2*>(out + (long)r * S + c) =
                make_float2(acc[mt][nt][0] / fmaxf(na0 * nb0, CEPS),
                            acc[mt][nt][1] / fmaxf(na0 * nb1, CEPS));
            *reinterpret_cast<float2*>(out + (long)(r + 8) * S + c) =
                make_float2(acc[mt][nt][2] / fmaxf(na1 * nb0, CEPS),
                            acc[mt][nt][3] / fmaxf(na1 * nb1, CEPS));
        }
    }
}

// ---------------- per-row logsumexp (cosines bounded -> no max pass) -------
__global__ void lse_kernel(const float* __restrict__ logits, int S, int off){
    const int tid = threadIdx.x;
    const long row = blockIdx.x;
    const float4* p = reinterpret_cast<const float4*>(logits + row * S);
    float s = 0.f;
    for (int i = tid; i < S / 4; i += 256) {
        float4 v = p[i];
        s += expf(v.x) + expf(v.y) + expf(v.z) + expf(v.w);
    }
    __shared__ float red[256];
    red[tid] = s;
    __syncthreads();
    for (int st = 128; st > 0; st >>= 1) {
        if (tid < st) red[tid] += red[tid + st];
        __syncthreads();
    }
    if (tid == 0) g_lse[off + row] = logf(red[0]);
}

// ---------------- recall GEMM + address_log finalize ----------------------
// out_addr_log = logit - lse (written back in place); P = exp(.) split hi/lo;
// recall[64,256] += P[64,Sk] @ V[Sk,256] via 3xbf16.
// BM=64, BN=256, BK=32, 256 thr, 8 warps as 2(m) x 4(n), warp tile 32x64.
__global__ __launch_bounds__(256) void recall_kernel(
    float* __restrict__ logits, const float* __restrict__ V,
    float* __restrict__ outR, int S, int lseoff)
{
    __shared__ __align__(16) __nv_bfloat16 Ph[64][40];
    __shared__ __align__(16) __nv_bfloat16 Pl[64][40];
    __shared__ __align__(16) __nv_bfloat16 Vh[32][264];
    __shared__ __align__(16) __nv_bfloat16 Vl[32][264];
    __shared__ float Ls[64];
    const int tid = threadIdx.x;
    const int warp = tid >> 5, lane = tid & 31;
    const int wm = warp >> 2, wn = warp & 3;
    const long bm = blockIdx.x;
    float* Lg = logits + bm * 64 * (long)S;

    if (tid < 64) Ls[tid] = g_lse[lseoff + bm * 64 + tid];
    __syncthreads();

    float acc[2][8][4];
    #pragma unroll
    for (int i = 0; i < 2; i++)
        #pragma unroll
        for (int j = 0; j < 8; j++)
            #pragma unroll
            for (int k = 0; k < 4; k++) acc[i][j][k] = 0.f;

    const int KB = S / 32;
    for (int kb = 0; kb < KB; ++kb) {
        #pragma unroll
        for (int j = 0; j < 2; ++j) {          // P tile 64x32 f32 + writeback
            int idx = tid + j * 256;
            int r = idx >> 3, c4 = idx & 7;
            float* gp = Lg + (long)r * S + kb * 32 + c4 * 4;
            float4 v = *reinterpret_cast<const float4*>(gp);
            float l = Ls[r];
            v.x -= l; v.y -= l; v.z -= l; v.w -= l;
            *reinterpret_cast<float4*>(gp) = v;  // final address_log
            float4 e = make_float4(__expf(v.x), __expf(v.y), __expf(v.z), __expf(v.w));
            uint2 hi, lo;
            split4(e, hi, lo);
            *reinterpret_cast<uint2*>(&Ph[r][c4 * 4]) = hi;
            *reinterpret_cast<uint2*>(&Pl[r][c4 * 4]) = lo;
        }
        #pragma unroll
        for (int j = 0; j < 8; ++j) {          // V tile 32x256 f32 -> hi/lo
            int idx = tid + j * 256;
            int r = idx >> 6, c4 = idx & 63;
            float4 v = *reinterpret_cast<const float4*>(V + (long)(kb * 32 + r) * 256 + c4 * 4);
            uint2 hi, lo;
            split4(v, hi, lo);
            *reinterpret_cast<uint2*>(&Vh[r][c4 * 4]) = hi;
            *reinterpret_cast<uint2*>(&Vl[r][c4 * 4]) = lo;
        }
        __syncthreads();
        #pragma unroll
        for (int kk = 0; kk < 2; ++kk) {
            unsigned ah[2][4], al[2][4], bh[4][4], bl[4][4];
            #pragma unroll
            for (int mt = 0; mt < 2; ++mt) {
                int r = wm * 32 + mt * 16 + (lane & 15);
                int c = kk * 16 + ((lane >> 4) << 3);
                ldsm4(ah[mt], &Ph[r][c]);
                ldsm4(al[mt], &Pl[r][c]);
            }
            #pragma unroll
            for (int np = 0; np < 4; ++np) {   // V is [k][n] row-major -> ldmatrix.trans
                int g = lane >> 3;
                int r = kk * 16 + ((g & 1) << 3) + (lane & 7);
                int c = wn * 64 + np * 16 + ((g >> 1) << 3);
                ldsm4t(bh[np], &Vh[r][c]);
                ldsm4t(bl[np], &Vl[r][c]);
            }
            #pragma unroll
            for (int mt = 0; mt < 2; ++mt)
                #pragma unroll
                for (int nt = 0; nt < 8; ++nt) {
                    unsigned h0 = bh[nt >> 1][(nt & 1) * 2], h1 = bh[nt >> 1][(nt & 1) * 2 + 1];
                    unsigned l0 = bl[nt >> 1][(nt & 1) * 2], l1 = bl[nt >> 1][(nt & 1) * 2 + 1];
                    mma16816(acc[mt][nt], ah[mt], h0, h1);
                    mma16816(acc[mt][nt], ah[mt], l0, l1);
                    mma16816(acc[mt][nt], al[mt], h0, h1);
                }
        }
        __syncthreads();
    }

    #pragma unroll
    for (int mt = 0; mt < 2; ++mt) {
        int r = (int)(bm * 64) + wm * 32 + mt * 16 + (lane >> 2);
        #pragma unroll
        for (int nt = 0; nt < 8; ++nt) {
            int c = wn * 64 + nt * 8 + (lane & 3) * 2;
            *reinterpret_cast<float2*>(outR + (long)r * 256 + c) =
                make_float2(acc[mt][nt][0], acc[mt][nt][1]);
            *reinterpret_cast<float2*>(outR + (long)(r + 8) * 256 + c) =
                make_float2(acc[mt][nt][2], acc[mt][nt][3]);
        }
    }
}

// ---------------------------------------------------------------------------
extern "C" void kernel_launch(void* const* d_in, const int* in_sizes, int n_in,
                              void* d_out, int out_size) {
    const float* face   = (const float*)d_in[0];
    const float* speech = (const float*)d_in[1];
    const float* svm    = (const float*)d_in[2];
    const float* fkm    = (const float*)d_in[3];
    const int C = 256;
    const int N = in_sizes[0] / C;   // 8192
    const int S = in_sizes[2] / C;   // 4096
    float* out = (float*)d_out;
    const long NC = (long)N * C;
    const long NS = (long)N * S;

    float* o_srec = out + NC;          // speech_emb_recall
    float* o_frec = out + 3 * NC;      // face_emb_recall
    float* o_slog = out + 4 * NC;      // speech_address_log (holds raw cos first)
    float* o_flog = out + 4 * NC + NS; // face_address_log

    // identity embeddings
    cudaMemcpyAsync(out,          speech, NC * sizeof(float), cudaMemcpyDeviceToDevice, 0);
    cudaMemcpyAsync(out + 2 * NC, face,   NC * sizeof(float), cudaMemcpyDeviceToDevice, 0);

    int rows = 2 * N + 2 * S;
    norms_kernel<<<(rows + 7) / 8, 256>>>(face, speech, svm, fkm, N, S);

    dim3 g2(S / 128, N / 128);
    logits_kernel<<<g2, 256>>>(speech, svm, o_slog, S, 0, 0);
    logits_kernel<<<g2, 256>>>(face,   fkm, o_flog, S, N, S);

    lse_kernel<<<N, 256>>>(o_slog, S, 0);
    lse_kernel<<<N, 256>>>(o_flog, S, N);

    // NOTE: both recalls use speech_value_memory, per reference.
    recall_kernel<<<N / 64, 256>>>(o_slog, svm, o_srec, S, 0);
    recall_kernel<<<N / 64, 256>>>(o_flog, svm, o_frec, S, N);
}

// round 3
// speedup vs baseline: 1.3569x; 1.3569x over previous
#include <cuda_runtime.h>
#include <cuda_fp16.h>
#include <cstdint>

#define CEPS 1e-8f
#define PSHIFT 8.0f
#define PSCALE 0.000335462627902512f  // exp(-8)

// scratch (N<=8192, S<=4096 for this problem)
static __device__ float g_norm_emb[16384]; // speech rows [0,N), face rows [N,2N)
static __device__ float g_norm_mem[8192];  // svm rows [0,S), fkm rows [S,2S)
static __device__ float g_lse[16384];      // speech rows [0,N), face rows [N,2N)

__device__ __forceinline__ unsigned pkh(float a, float b){
    __half2 h = __floats2half2_rn(a, b);
    return *reinterpret_cast<unsigned*>(&h);
}

__device__ __forceinline__ void ldsm4(unsigned r[4], const void* p){
    uint32_t a = (uint32_t)__cvta_generic_to_shared(p);
    asm volatile("ldmatrix.sync.aligned.m8n8.x4.shared.b16 {%0,%1,%2,%3}, [%4];\n"
        : "=r"(r[0]), "=r"(r[1]), "=r"(r[2]), "=r"(r[3]) : "r"(a));
}
__device__ __forceinline__ void ldsm4t(unsigned r[4], const void* p){
    uint32_t a = (uint32_t)__cvta_generic_to_shared(p);
    asm volatile("ldmatrix.sync.aligned.m8n8.x4.trans.shared.b16 {%0,%1,%2,%3}, [%4];\n"
        : "=r"(r[0]), "=r"(r[1]), "=r"(r[2]), "=r"(r[3]) : "r"(a));
}
__device__ __forceinline__ void mma16816(float c[4], const unsigned a[4], unsigned b0, unsigned b1){
    asm volatile("mma.sync.aligned.m16n8k16.row.col.f32.f16.f16.f32 "
        "{%0,%1,%2,%3}, {%4,%5,%6,%7}, {%8,%9}, {%0,%1,%2,%3};\n"
        : "+f"(c[0]), "+f"(c[1]), "+f"(c[2]), "+f"(c[3])
        : "r"(a[0]), "r"(a[1]), "r"(a[2]), "r"(a[3]), "r"(b0), "r"(b1));
}

// ---------------- row norms: one warp per row of 256 f32 ----------------
__global__ void norms_kernel(const float* __restrict__ face, const float* __restrict__ speech,
                             const float* __restrict__ svm, const float* __restrict__ fkm,
                             int N, int S){
    int warp = threadIdx.x >> 5, lane = threadIdx.x & 31;
    int rid = blockIdx.x * 8 + warp;
    int total = 2*N + 2*S;
    if (rid >= total) return;
    const float* src; float* dst;
    if (rid < N)            { src = speech + (long)rid * 256;         dst = g_norm_emb + rid; }
    else if (rid < 2*N)     { src = face   + (long)(rid - N) * 256;   dst = g_norm_emb + rid; }
    else if (rid < 2*N + S) { src = svm    + (long)(rid - 2*N) * 256; dst = g_norm_mem + (rid - 2*N); }
    else                    { src = fkm    + (long)(rid - 2*N - S) * 256; dst = g_norm_mem + (rid - 2*N); }
    const float4* p = reinterpret_cast<const float4*>(src);
    float4 v0 = p[lane], v1 = p[lane + 32];
    float s = v0.x*v0.x + v0.y*v0.y + v0.z*v0.z + v0.w*v0.w
            + v1.x*v1.x + v1.y*v1.y + v1.z*v1.z + v1.w*v1.w;
    #pragma unroll
    for (int o = 16; o; o >>= 1) s += __shfl_xor_sync(0xffffffffu, s, o);
    if (lane == 0) *dst = sqrtf(s);
}

// ---------------- logits GEMM: cos = (A@B^T)/max(|a||b|,eps) ----------------
// fp16 operands, f32 accumulate.
// BM=128, BN=128, BK=64, 256 threads, 8 warps as 4(m) x 2(n), warp tile 32x64.
__global__ __launch_bounds__(256) void logits_kernel(
    const float* __restrict__ A, const float* __restrict__ B,
    float* __restrict__ out, int S, int naoff, int nboff)
{
    __shared__ __align__(16) __half As[128][72];
    __shared__ __align__(16) __half Bs[128][72];
    const int tid = threadIdx.x;
    const int warp = tid >> 5, lane = tid & 31;
    const int wm = warp >> 1, wn = warp & 1;
    const long bm = blockIdx.y, bn = blockIdx.x;
    const float* Ab = A + bm * 128 * 256;
    const float* Bb = B + bn * 128 * 256;

    float acc[2][8][4];
    #pragma unroll
    for (int i = 0; i < 2; i++)
        #pragma unroll
        for (int j = 0; j < 8; j++)
            #pragma unroll
            for (int k = 0; k < 4; k++) acc[i][j][k] = 0.f;

    for (int kb = 0; kb < 4; ++kb) {
        #pragma unroll
        for (int j = 0; j < 8; ++j) {
            int idx = tid + j * 256;
            int r = idx >> 4, c4 = idx & 15;
            float4 v = *reinterpret_cast<const float4*>(Ab + r * 256 + kb * 64 + c4 * 4);
            *reinterpret_cast<uint2*>(&As[r][c4 * 4]) = make_uint2(pkh(v.x, v.y), pkh(v.z, v.w));
            float4 w = *reinterpret_cast<const float4*>(Bb + r * 256 + kb * 64 + c4 * 4);
            *reinterpret_cast<uint2*>(&Bs[r][c4 * 4]) = make_uint2(pkh(w.x, w.y), pkh(w.z, w.w));
        }
        __syncthreads();
        #pragma unroll
        for (int kk = 0; kk < 4; ++kk) {
            unsigned a[2][4], b[4][4];
            #pragma unroll
            for (int mt = 0; mt < 2; ++mt) {
                int r = wm * 32 + mt * 16 + (lane & 15);
                int c = kk * 16 + ((lane >> 4) << 3);
                ldsm4(a[mt], &As[r][c]);
            }
            #pragma unroll
            for (int np = 0; np < 4; ++np) {
                int g = lane >> 3;
                int r = wn * 64 + np * 16 + ((g >> 1) << 3) + (lane & 7);
                int c = kk * 16 + ((g & 1) << 3);
                ldsm4(b[np], &Bs[r][c]);
            }
            #pragma unroll
            for (int mt = 0; mt < 2; ++mt)
                #pragma unroll
                for (int nt = 0; nt < 8; ++nt)
                    mma16816(acc[mt][nt], a[mt], b[nt >> 1][(nt & 1) * 2], b[nt >> 1][(nt & 1) * 2 + 1]);
        }
        __syncthreads();
    }

    #pragma unroll
    for (int mt = 0; mt < 2; ++mt) {
        int r = (int)(bm * 128) + wm * 32 + mt * 16 + (lane >> 2);
        float na0 = g_norm_emb[naoff + r];
        float na1 = g_norm_emb[naoff + r + 8];
        #pragma unroll
        for (int nt = 0; nt < 8; ++nt) {
            int c = (int)(bn * 128) + wn * 64 + nt * 8 + (lane & 3) * 2;
            float nb0 = g_norm_mem[nboff + c];
            float nb1 = g_norm_mem[nboff + c + 1];
            *reinterpret_cast<float2*>(out + (long)r * S + c) =
                make_float2(acc[mt][nt][0] / fmaxf(na0 * nb0, CEPS),
                            acc[mt][nt][1] / fmaxf(na0 * nb1, CEPS));
            *reinterpret_cast<float2*>(out + (long)(r + 8) * S + c) =
                make_float2(acc[mt][nt][2] / fmaxf(na1 * nb0, CEPS),
                            acc[mt][nt][3] / fmaxf(na1 * nb1, CEPS));
        }
    }
}

// ---------------- per-row logsumexp (cosines bounded -> no max pass) -------
__global__ void lse_kernel(const float* __restrict__ logits, int S, int off){
    const int tid = threadIdx.x;
    const long row = blockIdx.x;
    const float4* p = reinterpret_cast<const float4*>(logits + row * S);
    float s = 0.f;
    for (int i = tid; i < S / 4; i += 256) {
        float4 v = p[i];
        s += __expf(v.x) + __expf(v.y) + __expf(v.z) + __expf(v.w);
    }
    __shared__ float red[256];
    red[tid] = s;
    __syncthreads();
    for (int st = 128; st > 0; st >>= 1) {
        if (tid < st) red[tid] += red[tid + st];
        __syncthreads();
    }
    if (tid == 0) g_lse[off + row] = logf(red[0]);
}

// ---------------- recall GEMM + address_log finalize ----------------------
// out_addr_log = logit - lse (written back in place); P' = exp(. + 8) fp16;
// recall[64,256] = exp(-8) * (P'[64,S] @ V[S,256]).
// BM=64, BN=256, BK=64, 256 thr, 8 warps as 2(m) x 4(n), warp tile 32x64.
__global__ __launch_bounds__(256) void recall_kernel(
    float* __restrict__ logits, const float* __restrict__ V,
    float* __restrict__ outR, int S, int lseoff)
{
    __shared__ __align__(16) __half Ps[64][72];
    __shared__ __align__(16) __half Vs[64][264];
    __shared__ float Ls[64];
    const int tid = threadIdx.x;
    const int warp = tid >> 5, lane = tid & 31;
    const int wm = warp >> 2, wn = warp & 3;
    const long bm = blockIdx.x;
    float* Lg = logits + bm * 64 * (long)S;

    if (tid < 64) Ls[tid] = g_lse[lseoff + bm * 64 + tid];
    __syncthreads();

    float acc[2][8][4];
    #pragma unroll
    for (int i = 0; i < 2; i++)
        #pragma unroll
        for (int j = 0; j < 8; j++)
            #pragma unroll
            for (int k = 0; k < 4; k++) acc[i][j][k] = 0.f;

    const int KB = S / 64;
    for (int kb = 0; kb < KB; ++kb) {
        #pragma unroll
        for (int j = 0; j < 4; ++j) {          // P tile 64x64 f32 + writeback
            int idx = tid + j * 256;
            int r = idx >> 4, c4 = idx & 15;
            float* gp = Lg + (long)r * S + kb * 64 + c4 * 4;
            float4 v = *reinterpret_cast<const float4*>(gp);
            float l = Ls[r];
            v.x -= l; v.y -= l; v.z -= l; v.w -= l;
            *reinterpret_cast<float4*>(gp) = v;  // final address_log
            *reinterpret_cast<uint2*>(&Ps[r][c4 * 4]) =
                make_uint2(pkh(__expf(v.x + PSHIFT), __expf(v.y + PSHIFT)),
                           pkh(__expf(v.z + PSHIFT), __expf(v.w + PSHIFT)));
        }
        #pragma unroll
        for (int j = 0; j < 16; ++j) {         // V tile 64x256 f32 -> fp16
            int idx = tid + j * 256;
            int r = idx >> 6, c4 = idx & 63;
            float4 v = *reinterpret_cast<const float4*>(V + (long)(kb * 64 + r) * 256 + c4 * 4);
            *reinterpret_cast<uint2*>(&Vs[r][c4 * 4]) = make_uint2(pkh(v.x, v.y), pkh(v.z, v.w));
        }
        __syncthreads();
        #pragma unroll
        for (int kk = 0; kk < 4; ++kk) {
            unsigned a[2][4], b[4][4];
            #pragma unroll
            for (int mt = 0; mt < 2; ++mt) {
                int r = wm * 32 + mt * 16 + (lane & 15);
                int c = kk * 16 + ((lane >> 4) << 3);
                ldsm4(a[mt], &Ps[r][c]);
            }
            #pragma unroll
            for (int np = 0; np < 4; ++np) {   // V is [k][n] row-major -> ldmatrix.trans
                int g = lane >> 3;
                int r = kk * 16 + ((g & 1) << 3) + (lane & 7);
                int c = wn * 64 + np * 16 + ((g >> 1) << 3);
                ldsm4t(b[np], &Vs[r][c]);
            }
            #pragma unroll
            for (int mt = 0; mt < 2; ++mt)
                #pragma unroll
                for (int nt = 0; nt < 8; ++nt)
                    mma16816(acc[mt][nt], a[mt], b[nt >> 1][(nt & 1) * 2], b[nt >> 1][(nt & 1) * 2 + 1]);
        }
        __syncthreads();
    }

    #pragma unroll
    for (int mt = 0; mt < 2; ++mt) {
        int r = (int)(bm * 64) + wm * 32 + mt * 16 + (lane >> 2);
        #pragma unroll
        for (int nt = 0; nt < 8; ++nt) {
            int c = wn * 64 + nt * 8 + (lane & 3) * 2;
            *reinterpret_cast<float2*>(outR + (long)r * 256 + c) =
                make_float2(acc[mt][nt][0] * PSCALE, acc[mt][nt][1] * PSCALE);
            *reinterpret_cast<float2*>(outR + (long)(r + 8) * 256 + c) =
                make_float2(acc[mt][nt][2] * PSCALE, acc[mt][nt][3] * PSCALE);
        }
    }
}

// ---------------------------------------------------------------------------
extern "C" void kernel_launch(void* const* d_in, const int* in_sizes, int n_in,
                              void* d_out, int out_size) {
    const float* face   = (const float*)d_in[0];
    const float* speech = (const float*)d_in[1];
    const float* svm    = (const float*)d_in[2];
    const float* fkm    = (const float*)d_in[3];
    const int C = 256;
    const int N = in_sizes[0] / C;   // 8192
    const int S = in_sizes[2] / C;   // 4096
    float* out = (float*)d_out;
    const long NC = (long)N * C;
    const long NS = (long)N * S;

    float* o_srec = out + NC;          // speech_emb_recall
    float* o_frec = out + 3 * NC;      // face_emb_recall
    float* o_slog = out + 4 * NC;      // speech_address_log (holds raw cos first)
    float* o_flog = out + 4 * NC + NS; // face_address_log

    // identity embeddings
    cudaMemcpyAsync(out,          speech, NC * sizeof(float), cudaMemcpyDeviceToDevice, 0);
    cudaMemcpyAsync(out + 2 * NC, face,   NC * sizeof(float), cudaMemcpyDeviceToDevice, 0);

    int rows = 2 * N + 2 * S;
    norms_kernel<<<(rows + 7) / 8, 256>>>(face, speech, svm, fkm, N, S);

    dim3 g2(S / 128, N / 128);
    logits_kernel<<<g2, 256>>>(speech, svm, o_slog, S, 0, 0);
    logits_kernel<<<g2, 256>>>(face,   fkm, o_flog, S, N, S);

    lse_kernel<<<N, 256>>>(o_slog, S, 0);
    lse_kernel<<<N, 256>>>(o_flog, S, N);

    // NOTE: both recalls use speech_value_memory, per reference.
    recall_kernel<<<N / 64, 256>>>(o_slog, svm, o_srec, S, 0);
    recall_kernel<<<N / 64, 256>>>(o_flog, svm, o_frec, S, N);
}

// round 4
// speedup vs baseline: 3.0964x; 2.2820x over previous
#include <cuda_runtime.h>
#include <cuda_fp16.h>
#include <cstdint>

#define CEPS 1e-8f
#define PSHIFT 8.0f
#define PSCALE 0.000335462627902512f  // exp(-8)

// scratch (N<=8192, S<=4096 for this problem)
static __device__ float g_norm_emb[16384]; // speech rows [0,N), face rows [N,2N)
static __device__ float g_norm_mem[8192];  // svm rows [0,S), fkm rows [S,2S)
static __device__ float g_lse[16384];      // speech rows [0,N), face rows [N,2N)
static __device__ __half g_sp_h[8192 * 256];
static __device__ __half g_fa_h[8192 * 256];
static __device__ __half g_svm_h[4096 * 256];
static __device__ __half g_fkm_h[4096 * 256];

__device__ __forceinline__ unsigned pkh(float a, float b){
    __half2 h = __floats2half2_rn(a, b);
    return *reinterpret_cast<unsigned*>(&h);
}
__device__ __forceinline__ void cpa16(uint32_t dst, const void* src){
    asm volatile("cp.async.cg.shared.global [%0], [%1], 16;\n" :: "r"(dst), "l"(src));
}
#define CP_COMMIT asm volatile("cp.async.commit_group;\n" ::: "memory")
#define CP_WAIT(n) asm volatile("cp.async.wait_group %0;\n" :: "n"(n) : "memory")

__device__ __forceinline__ void ldsm4(unsigned r[4], const void* p){
    uint32_t a = (uint32_t)__cvta_generic_to_shared(p);
    asm volatile("ldmatrix.sync.aligned.m8n8.x4.shared.b16 {%0,%1,%2,%3}, [%4];\n"
        : "=r"(r[0]), "=r"(r[1]), "=r"(r[2]), "=r"(r[3]) : "r"(a));
}
__device__ __forceinline__ void ldsm4t(unsigned r[4], const void* p){
    uint32_t a = (uint32_t)__cvta_generic_to_shared(p);
    asm volatile("ldmatrix.sync.aligned.m8n8.x4.trans.shared.b16 {%0,%1,%2,%3}, [%4];\n"
        : "=r"(r[0]), "=r"(r[1]), "=r"(r[2]), "=r"(r[3]) : "r"(a));
}
__device__ __forceinline__ void mma16816(float c[4], const unsigned a[4], unsigned b0, unsigned b1){
    asm volatile("mma.sync.aligned.m16n8k16.row.col.f32.f16.f16.f32 "
        "{%0,%1,%2,%3}, {%4,%5,%6,%7}, {%8,%9}, {%0,%1,%2,%3};\n"
        : "+f"(c[0]), "+f"(c[1]), "+f"(c[2]), "+f"(c[3])
        : "r"(a[0]), "r"(a[1]), "r"(a[2]), "r"(a[3]), "r"(b0), "r"(b1));
}

// ------------- fused convert(f32->f16) + row norms: one warp per row -------
__global__ void convert_norms_kernel(const float* __restrict__ face, const float* __restrict__ speech,
                                     const float* __restrict__ svm, const float* __restrict__ fkm,
                                     int N, int S){
    int warp = threadIdx.x >> 5, lane = threadIdx.x & 31;
    int rid = blockIdx.x * 8 + warp;
    int total = 2*N + 2*S;
    if (rid >= total) return;
    const float* src; float* ndst; __half* hdst;
    if (rid < N)            { src = speech + (long)rid * 256; ndst = g_norm_emb + rid; hdst = g_sp_h + (long)rid * 256; }
    else if (rid < 2*N)     { int r = rid - N; src = face + (long)r * 256; ndst = g_norm_emb + rid; hdst = g_fa_h + (long)r * 256; }
    else if (rid < 2*N + S) { int r = rid - 2*N; src = svm + (long)r * 256; ndst = g_norm_mem + r; hdst = g_svm_h + (long)r * 256; }
    else                    { int r = rid - 2*N - S; src = fkm + (long)r * 256; ndst = g_norm_mem + (rid - 2*N); hdst = g_fkm_h + (long)r * 256; }
    const float4* p = reinterpret_cast<const float4*>(src);
    float4 v0 = p[lane], v1 = p[lane + 32];
    uint2* up = reinterpret_cast<uint2*>(hdst);
    up[lane]      = make_uint2(pkh(v0.x, v0.y), pkh(v0.z, v0.w));
    up[lane + 32] = make_uint2(pkh(v1.x, v1.y), pkh(v1.z, v1.w));
    float s = v0.x*v0.x + v0.y*v0.y + v0.z*v0.z + v0.w*v0.w
            + v1.x*v1.x + v1.y*v1.y + v1.z*v1.z + v1.w*v1.w;
    #pragma unroll
    for (int o = 16; o; o >>= 1) s += __shfl_xor_sync(0xffffffffu, s, o);
    if (lane == 0) *ndst = sqrtf(s);
}

// ---------------- logits GEMM: cos = (A@B^T)/max(|a||b|,eps) ----------------
// fp16 operands via cp.async double-buffer. BM=128, BN=128, BK=64, 256 thr,
// 8 warps as 4(m) x 2(n), warp tile 32x64. Dynamic smem: 2*2*128*72*2 = 73728B.
__global__ __launch_bounds__(256) void logits_kernel(
    float* __restrict__ out, int N, int S, int which)
{
    extern __shared__ __align__(16) char sm[];
    __half* As = (__half*)sm;              // [2][128][72]
    __half* Bs = (__half*)(sm + 36864);    // [2][128][72]
    const __half* A = which ? g_fa_h : g_sp_h;
    const __half* B = which ? g_fkm_h : g_svm_h;
    const int naoff = which ? N : 0, nboff = which ? S : 0;
    const int tid = threadIdx.x;
    const int warp = tid >> 5, lane = tid & 31;
    const int wm = warp >> 1, wn = warp & 1;
    const long bm = blockIdx.y, bn = blockIdx.x;
    const __half* Ab = A + bm * 128 * 256;
    const __half* Bb = B + bn * 128 * 256;
    uint32_t sa = (uint32_t)__cvta_generic_to_shared(As);
    uint32_t sb = (uint32_t)__cvta_generic_to_shared(Bs);
    const int lr = tid >> 3, lc = (tid & 7) * 8;   // chunk: 8 halves

    float acc[2][8][4] = {};

    // prologue: stage 0
    #pragma unroll
    for (int i = 0; i < 4; i++) {
        int r = lr + i * 32;
        cpa16(sa + (unsigned)(r * 72 + lc) * 2, Ab + r * 256 + lc);
        cpa16(sb + (unsigned)(r * 72 + lc) * 2, Bb + r * 256 + lc);
    }
    CP_COMMIT;

    for (int kb = 0; kb < 4; ++kb) {
        if (kb < 3) {
            int st = (kb + 1) & 1;
            #pragma unroll
            for (int i = 0; i < 4; i++) {
                int r = lr + i * 32;
                cpa16(sa + (unsigned)(st * 9216 + r * 72 + lc) * 2, Ab + r * 256 + (kb + 1) * 64 + lc);
                cpa16(sb + (unsigned)(st * 9216 + r * 72 + lc) * 2, Bb + r * 256 + (kb + 1) * 64 + lc);
            }
        }
        CP_COMMIT;
        CP_WAIT(1);
        __syncthreads();
        const __half* Ast = As + (kb & 1) * 9216;
        const __half* Bst = Bs + (kb & 1) * 9216;
        #pragma unroll
        for (int kk = 0; kk < 4; ++kk) {
            unsigned a[2][4], b[4][4];
            #pragma unroll
            for (int mt = 0; mt < 2; ++mt) {
                int r = wm * 32 + mt * 16 + (lane & 15);
                int c = kk * 16 + ((lane >> 4) << 3);
                ldsm4(a[mt], Ast + r * 72 + c);
            }
            #pragma unroll
            for (int np = 0; np < 4; ++np) {
                int g = lane >> 3;
                int r = wn * 64 + np * 16 + ((g >> 1) << 3) + (lane & 7);
                int c = kk * 16 + ((g & 1) << 3);
                ldsm4(b[np], Bst + r * 72 + c);
            }
            #pragma unroll
            for (int mt = 0; mt < 2; ++mt)
                #pragma unroll
                for (int nt = 0; nt < 8; ++nt)
                    mma16816(acc[mt][nt], a[mt], b[nt >> 1][(nt & 1) * 2], b[nt >> 1][(nt & 1) * 2 + 1]);
        }
        __syncthreads();
    }

    #pragma unroll
    for (int mt = 0; mt < 2; ++mt) {
        int r = (int)(bm * 128) + wm * 32 + mt * 16 + (lane >> 2);
        float na0 = g_norm_emb[naoff + r];
        float na1 = g_norm_emb[naoff + r + 8];
        #pragma unroll
        for (int nt = 0; nt < 8; ++nt) {
            int c = (int)(bn * 128) + wn * 64 + nt * 8 + (lane & 3) * 2;
            float nb0 = g_norm_mem[nboff + c];
            float nb1 = g_norm_mem[nboff + c + 1];
            *reinterpret_cast<float2*>(out + (long)r * S + c) =
                make_float2(acc[mt][nt][0] / fmaxf(na0 * nb0, CEPS),
                            acc[mt][nt][1] / fmaxf(na0 * nb1, CEPS));
            *reinterpret_cast<float2*>(out + (long)(r + 8) * S + c) =
                make_float2(acc[mt][nt][2] / fmaxf(na1 * nb0, CEPS),
                            acc[mt][nt][3] / fmaxf(na1 * nb1, CEPS));
        }
    }
}

// ---------------- per-row logsumexp (cosines bounded -> no max pass) -------
__global__ void lse_kernel(const float* __restrict__ logits, int S, int off){
    const int tid = threadIdx.x;
    const long row = blockIdx.x;
    const float4* p = reinterpret_cast<const float4*>(logits + row * S);
    float s = 0.f;
    for (int i = tid; i < S / 4; i += 256) {
        float4 v = p[i];
        s += __expf(v.x) + __expf(v.y) + __expf(v.z) + __expf(v.w);
    }
    __shared__ float red[256];
    red[tid] = s;
    __syncthreads();
    for (int st = 128; st > 0; st >>= 1) {
        if (tid < st) red[tid] += red[tid + st];
        __syncthreads();
    }
    if (tid == 0) g_lse[off + row] = logf(red[0]);
}

// ---------------- recall GEMM + address_log finalize ----------------------
// Double-buffered cp.async for V(f16) and logits(f32) tiles.
// out_addr_log = logit - lse (written back); P' = exp(.+8) fp16;
// recall = exp(-8) * (P' @ V). BM=64, BN=256, BK=64, 256 thr, warps 2x4.
// Dyn smem: Vs 2*64*264*2=67584 + Lf 2*64*68*4=34816 + Ps 2*64*72*2=18432 + Ls 256
__global__ __launch_bounds__(256) void recall_kernel(
    float* __restrict__ logits, float* __restrict__ outR, int S, int lseoff)
{
    extern __shared__ __align__(16) char sm[];
    __half* Vs = (__half*)sm;                        // [2][64][264]
    float*  Lf = (float*)(sm + 67584);               // [2][64][68]
    __half* Ps = (__half*)(sm + 67584 + 34816);      // [2][64][72]
    float*  Ls = (float*)(sm + 67584 + 34816 + 18432);
    const __half* V = g_svm_h;
    const int tid = threadIdx.x;
    const int warp = tid >> 5, lane = tid & 31;
    const int wm = warp >> 2, wn = warp & 3;
    const long bm = blockIdx.x;
    float* Lg = logits + bm * 64 * (long)S;
    uint32_t sv = (uint32_t)__cvta_generic_to_shared(Vs);
    uint32_t sl = (uint32_t)__cvta_generic_to_shared(Lf);

    if (tid < 64) Ls[tid] = g_lse[lseoff + bm * 64 + tid];

    float acc[2][8][4] = {};

    // prologue loads stage 0
    #pragma unroll
    for (int i = 0; i < 8; i++) {
        int idx = tid + i * 256, r = idx >> 5, c = idx & 31;
        cpa16(sv + (unsigned)(r * 264 + c * 8) * 2, V + (long)r * 256 + c * 8);
    }
    #pragma unroll
    for (int i = 0; i < 4; i++) {
        int idx = tid + i * 256, r = idx >> 4, c = idx & 15;
        cpa16(sl + (unsigned)(r * 68 + c * 4) * 4, Lg + (long)r * S + c * 4);
    }
    CP_COMMIT;

    const int KB = S / 64;
    for (int kb = 0; kb < KB; ++kb) {
        CP_WAIT(0);
        __syncthreads();
        if (kb < KB - 1) {
            int st = (kb + 1) & 1;
            #pragma unroll
            for (int i = 0; i < 8; i++) {
                int idx = tid + i * 256, r = idx >> 5, c = idx & 31;
                cpa16(sv + (unsigned)(st * 16896 + r * 264 + c * 8) * 2,
                      V + (long)((kb + 1) * 64 + r) * 256 + c * 8);
            }
            #pragma unroll
            for (int i = 0; i < 4; i++) {
                int idx = tid + i * 256, r = idx >> 4, c = idx & 15;
                cpa16(sl + (unsigned)(st * 4352 + r * 68 + c * 4) * 4,
                      Lg + (long)r * S + (kb + 1) * 64 + c * 4);
            }
            CP_COMMIT;
        }
        const int st = kb & 1;
        // build Ps from Lf + writeback address_log
        #pragma unroll
        for (int i = 0; i < 4; i++) {
            int idx = tid + i * 256, r = idx >> 4, c = idx & 15;
            float4 v = *reinterpret_cast<float4*>(Lf + st * 4352 + r * 68 + c * 4);
            float l = Ls[r];
            v.x -= l; v.y -= l; v.z -= l; v.w -= l;
            *reinterpret_cast<float4*>(Lg + (long)r * S + kb * 64 + c * 4) = v;
            *reinterpret_cast<uint2*>(Ps + st * 4608 + r * 72 + c * 4) =
                make_uint2(pkh(__expf(v.x + PSHIFT), __expf(v.y + PSHIFT)),
                           pkh(__expf(v.z + PSHIFT), __expf(v.w + PSHIFT)));
        }
        __syncthreads();
        const __half* Pst = Ps + st * 4608;
        const __half* Vst = Vs + st * 16896;
        #pragma unroll
        for (int kk = 0; kk < 4; ++kk) {
            unsigned a[2][4], b[4][4];
            #pragma unroll
            for (int mt = 0; mt < 2; ++mt) {
                int r = wm * 32 + mt * 16 + (lane & 15);
                int c = kk * 16 + ((lane >> 4) << 3);
                ldsm4(a[mt], Pst + r * 72 + c);
            }
            #pragma unroll
            for (int np = 0; np < 4; ++np) {   // V rows=k, cols=n -> trans
                int g = lane >> 3;
                int r = kk * 16 + ((g & 1) << 3) + (lane & 7);
                int c = wn * 64 + np * 16 + ((g >> 1) << 3);
                ldsm4t(b[np], Vst + r * 264 + c);
            }
            #pragma unroll
            for (int mt = 0; mt < 2; ++mt)
                #pragma unroll
                for (int nt = 0; nt < 8; ++nt)
                    mma16816(acc[mt][nt], a[mt], b[nt >> 1][(nt & 1) * 2], b[nt >> 1][(nt & 1) * 2 + 1]);
        }
        __syncthreads();
    }

    #pragma unroll
    for (int mt = 0; mt < 2; ++mt) {
        int r = (int)(bm * 64) + wm * 32 + mt * 16 + (lane >> 2);
        #pragma unroll
        for (int nt = 0; nt < 8; ++nt) {
            int c = wn * 64 + nt * 8 + (lane & 3) * 2;
            *reinterpret_cast<float2*>(outR + (long)r * 256 + c) =
                make_float2(acc[mt][nt][0] * PSCALE, acc[mt][nt][1] * PSCALE);
            *reinterpret_cast<float2*>(outR + (long)(r + 8) * 256 + c) =
                make_float2(acc[mt][nt][2] * PSCALE, acc[mt][nt][3] * PSCALE);
        }
    }
}

// ---------------------------------------------------------------------------
static const int LOG_SMEM = 73728;
static const int REC_SMEM = 67584 + 34816 + 18432 + 256;

extern "C" void kernel_launch(void* const* d_in, const int* in_sizes, int n_in,
                              void* d_out, int out_size) {
    const float* face   = (const float*)d_in[0];
    const float* speech = (const float*)d_in[1];
    const float* svm    = (const float*)d_in[2];
    const float* fkm    = (const float*)d_in[3];
    const int C = 256;
    const int N = in_sizes[0] / C;   // 8192
    const int S = in_sizes[2] / C;   // 4096
    float* out = (float*)d_out;
    const long NC = (long)N * C;
    const long NS = (long)N * S;

    float* o_srec = out + NC;          // speech_emb_recall
    float* o_frec = out + 3 * NC;      // face_emb_recall
    float* o_slog = out + 4 * NC;      // speech_address_log (holds raw cos first)
    float* o_flog = out + 4 * NC + NS; // face_address_log

    cudaFuncSetAttribute(logits_kernel, cudaFuncAttributeMaxDynamicSharedMemorySize, LOG_SMEM);
    cudaFuncSetAttribute(recall_kernel, cudaFuncAttributeMaxDynamicSharedMemorySize, REC_SMEM);

    // identity embeddings
    cudaMemcpyAsync(out,          speech, NC * sizeof(float), cudaMemcpyDeviceToDevice, 0);
    cudaMemcpyAsync(out + 2 * NC, face,   NC * sizeof(float), cudaMemcpyDeviceToDevice, 0);

    int rows = 2 * N + 2 * S;
    convert_norms_kernel<<<(rows + 7) / 8, 256>>>(face, speech, svm, fkm, N, S);

    dim3 g2(S / 128, N / 128);
    logits_kernel<<<g2, 256, LOG_SMEM>>>(o_slog, N, S, 0);
    logits_kernel<<<g2, 256, LOG_SMEM>>>(o_flog, N, S, 1);

    lse_kernel<<<N, 256>>>(o_slog, S, 0);
    lse_kernel<<<N, 256>>>(o_flog, S, N);

    // NOTE: both recalls use speech_value_memory, per reference.
    recall_kernel<<<N / 64, 256, REC_SMEM>>>(o_slog, o_srec, S, 0);
    recall_kernel<<<N / 64, 256, REC_SMEM>>>(o_flog, o_frec, S, N);
}

// round 7
// speedup vs baseline: 3.4801x; 1.1239x over previous
#include <cuda_runtime.h>
#include <cuda_fp16.h>
#include <cstdint>

#define CEPS 1e-8f
#define PSHIFT 8.0f
#define PSCALE 0.000335462627902512f  // exp(-8)

// scratch (N<=8192, S<=4096 for this problem)
static __device__ float g_norm_emb[16384]; // speech rows [0,N), face rows [N,2N)
static __device__ float g_norm_mem[8192];  // svm rows [0,S), fkm rows [S,2S)
static __device__ float g_partial[16384 * 64]; // per-row partial sumexp (64 chunks/row)
static __device__ __half g_sp_h[8192 * 256];
static __device__ __half g_fa_h[8192 * 256];
static __device__ __half g_svm_h[4096 * 256];
static __device__ __half g_fkm_h[4096 * 256];

__device__ __forceinline__ unsigned pkh(float a, float b){
    __half2 h = __floats2half2_rn(a, b);
    return *reinterpret_cast<unsigned*>(&h);
}
__device__ __forceinline__ void cpa16(uint32_t dst, const void* src){
    asm volatile("cp.async.cg.shared.global [%0], [%1], 16;\n" :: "r"(dst), "l"(src));
}
#define CP_COMMIT asm volatile("cp.async.commit_group;\n" ::: "memory")
#define CP_WAIT(n) asm volatile("cp.async.wait_group %0;\n" :: "n"(n) : "memory")

__device__ __forceinline__ void ldsm4(unsigned r[4], const void* p){
    uint32_t a = (uint32_t)__cvta_generic_to_shared(p);
    asm volatile("ldmatrix.sync.aligned.m8n8.x4.shared.b16 {%0,%1,%2,%3}, [%4];\n"
        : "=r"(r[0]), "=r"(r[1]), "=r"(r[2]), "=r"(r[3]) : "r"(a));
}
__device__ __forceinline__ void ldsm4t(unsigned r[4], const void* p){
    uint32_t a = (uint32_t)__cvta_generic_to_shared(p);
    asm volatile("ldmatrix.sync.aligned.m8n8.x4.trans.shared.b16 {%0,%1,%2,%3}, [%4];\n"
        : "=r"(r[0]), "=r"(r[1]), "=r"(r[2]), "=r"(r[3]) : "r"(a));
}
__device__ __forceinline__ void mma16816(float c[4], const unsigned a[4], unsigned b0, unsigned b1){
    asm volatile("mma.sync.aligned.m16n8k16.row.col.f32.f16.f16.f32 "
        "{%0,%1,%2,%3}, {%4,%5,%6,%7}, {%8,%9}, {%0,%1,%2,%3};\n"
        : "+f"(c[0]), "+f"(c[1]), "+f"(c[2]), "+f"(c[3])
        : "r"(a[0]), "r"(a[1]), "r"(a[2]), "r"(a[3]), "r"(b0), "r"(b1));
}

// ------------- fused convert(f32->f16) + row norms: one warp per row -------
__global__ void convert_norms_kernel(const float* __restrict__ face, const float* __restrict__ speech,
                                     const float* __restrict__ svm, const float* __restrict__ fkm,
                                     int N, int S){
    int warp = threadIdx.x >> 5, lane = threadIdx.x & 31;
    int rid = blockIdx.x * 8 + warp;
    int total = 2*N + 2*S;
    if (rid >= total) return;
    const float* src; float* ndst; __half* hdst;
    if (rid < N)            { src = speech + (long)rid * 256; ndst = g_norm_emb + rid; hdst = g_sp_h + (long)rid * 256; }
    else if (rid < 2*N)     { int r = rid - N; src = face + (long)r * 256; ndst = g_norm_emb + rid; hdst = g_fa_h + (long)r * 256; }
    else if (rid < 2*N + S) { int r = rid - 2*N; src = svm + (long)r * 256; ndst = g_norm_mem + r; hdst = g_svm_h + (long)r * 256; }
    else                    { int r = rid - 2*N - S; src = fkm + (long)r * 256; ndst = g_norm_mem + (rid - 2*N); hdst = g_fkm_h + (long)r * 256; }
    const float4* p = reinterpret_cast<const float4*>(src);
    float4 v0 = p[lane], v1 = p[lane + 32];
    uint2* up = reinterpret_cast<uint2*>(hdst);
    up[lane]      = make_uint2(pkh(v0.x, v0.y), pkh(v0.z, v0.w));
    up[lane + 32] = make_uint2(pkh(v1.x, v1.y), pkh(v1.z, v1.w));
    float s = v0.x*v0.x + v0.y*v0.y + v0.z*v0.z + v0.w*v0.w
            + v1.x*v1.x + v1.y*v1.y + v1.z*v1.z + v1.w*v1.w;
    #pragma unroll
    for (int o = 16; o; o >>= 1) s += __shfl_xor_sync(0xffffffffu, s, o);
    if (lane == 0) *ndst = sqrtf(s);
}

// ---------------- logits GEMM: cos = (A@B^T)/max(|a||b|,eps) ----------------
// fp16 operands via cp.async double-buffer. BM=128, BN=128, BK=64, 256 thr,
// 8 warps as 4(m) x 2(n), warp tile 32x64. blockIdx.z selects speech/face.
// Fused lse: per-thread Sum(exp(cos)) over its fragment cols, quad-reduced,
// written to g_partial[row][bn*2+wn] (64 chunks per row, fixed order).
__global__ __launch_bounds__(256) void logits_kernel(
    float* __restrict__ out0, float* __restrict__ out1, int N, int S)
{
    extern __shared__ __align__(16) char sm[];
    __half* As = (__half*)sm;              // [2][128][72]
    __half* Bs = (__half*)(sm + 36864);    // [2][128][72]
    const int which = blockIdx.z;
    float* out = which ? out1 : out0;
    const __half* A = which ? g_fa_h : g_sp_h;
    const __half* B = which ? g_fkm_h : g_svm_h;
    const int naoff = which ? N : 0, nboff = which ? S : 0;
    const int tid = threadIdx.x;
    const int warp = tid >> 5, lane = tid & 31;
    const int wm = warp >> 1, wn = warp & 1;
    const long bm = blockIdx.y, bn = blockIdx.x;
    const __half* Ab = A + bm * 128 * 256;
    const __half* Bb = B + bn * 128 * 256;
    uint32_t sa = (uint32_t)__cvta_generic_to_shared(As);
    uint32_t sb = (uint32_t)__cvta_generic_to_shared(Bs);
    const int lr = tid >> 3, lc = (tid & 7) * 8;   // chunk: 8 halves

    float acc[2][8][4] = {};

    // prologue: stage 0
    #pragma unroll
    for (int i = 0; i < 4; i++) {
        int r = lr + i * 32;
        cpa16(sa + (unsigned)(r * 72 + lc) * 2, Ab + r * 256 + lc);
        cpa16(sb + (unsigned)(r * 72 + lc) * 2, Bb + r * 256 + lc);
    }
    CP_COMMIT;

    for (int kb = 0; kb < 4; ++kb) {
        if (kb < 3) {
            int st = (kb + 1) & 1;
            #pragma unroll
            for (int i = 0; i < 4; i++) {
                int r = lr + i * 32;
                cpa16(sa + (unsigned)(st * 9216 + r * 72 + lc) * 2, Ab + r * 256 + (kb + 1) * 64 + lc);
                cpa16(sb + (unsigned)(st * 9216 + r * 72 + lc) * 2, Bb + r * 256 + (kb + 1) * 64 + lc);
            }
        }
        CP_COMMIT;
        CP_WAIT(1);
        __syncthreads();
        const __half* Ast = As + (kb & 1) * 9216;
        const __half* Bst = Bs + (kb & 1) * 9216;
        #pragma unroll
        for (int kk = 0; kk < 4; ++kk) {
            unsigned a[2][4], b[4][4];
            #pragma unroll
            for (int mt = 0; mt < 2; ++mt) {
                int r = wm * 32 + mt * 16 + (lane & 15);
                int c = kk * 16 + ((lane >> 4) << 3);
                ldsm4(a[mt], Ast + r * 72 + c);
            }
            #pragma unroll
            for (int np = 0; np < 4; ++np) {
                int g = lane >> 3;
                int r = wn * 64 + np * 16 + ((g >> 1) << 3) + (lane & 7);
                int c = kk * 16 + ((g & 1) << 3);
                ldsm4(b[np], Bst + r * 72 + c);
            }
            #pragma unroll
            for (int mt = 0; mt < 2; ++mt)
                #pragma unroll
                for (int nt = 0; nt < 8; ++nt)
                    mma16816(acc[mt][nt], a[mt], b[nt >> 1][(nt & 1) * 2], b[nt >> 1][(nt & 1) * 2 + 1]);
        }
        __syncthreads();
    }

    #pragma unroll
    for (int mt = 0; mt < 2; ++mt) {
        int r = (int)(bm * 128) + wm * 32 + mt * 16 + (lane >> 2);
        float na0 = g_norm_emb[naoff + r];
        float na1 = g_norm_emb[naoff + r + 8];
        float ps0 = 0.f, ps1 = 0.f;
        #pragma unroll
        for (int nt = 0; nt < 8; ++nt) {
            int c = (int)(bn * 128) + wn * 64 + nt * 8 + (lane & 3) * 2;
            float nb0 = g_norm_mem[nboff + c];
            float nb1 = g_norm_mem[nboff + c + 1];
            float c00 = acc[mt][nt][0] / fmaxf(na0 * nb0, CEPS);
            float c01 = acc[mt][nt][1] / fmaxf(na0 * nb1, CEPS);
            float c10 = acc[mt][nt][2] / fmaxf(na1 * nb0, CEPS);
            float c11 = acc[mt][nt][3] / fmaxf(na1 * nb1, CEPS);
            ps0 += __expf(c00) + __expf(c01);
            ps1 += __expf(c10) + __expf(c11);
            *reinterpret_cast<float2*>(out + (long)r * S + c) = make_float2(c00, c01);
            *reinterpret_cast<float2*>(out + (long)(r + 8) * S + c) = make_float2(c10, c11);
        }
        // quad reduction (lanes differing in bits 0,1 share the same rows)
        ps0 += __shfl_xor_sync(0xffffffffu, ps0, 1);
        ps0 += __shfl_xor_sync(0xffffffffu, ps0, 2);
        ps1 += __shfl_xor_sync(0xffffffffu, ps1, 1);
        ps1 += __shfl_xor_sync(0xffffffffu, ps1, 2);
        if ((lane & 3) == 0) {
            int chunk = (int)bn * 2 + wn;
            g_partial[(long)(naoff + r) * 64 + chunk] = ps0;
            g_partial[(long)(naoff + r + 8) * 64 + chunk] = ps1;
        }
    }
}

// ---------------- recall GEMM + address_log finalize ----------------------
// blockIdx.y selects speech/face (merged launch). Ls = log(sum of 64
// partials, fixed order). out_addr_log = logit - lse (written back);
// P' = exp(.+8) fp16; recall = exp(-8) * (P' @ svm). BM=64, BN=256, BK=64.
__global__ __launch_bounds__(256) void recall_kernel(
    float* __restrict__ logits0, float* __restrict__ logits1,
    float* __restrict__ outR0, float* __restrict__ outR1, int N, int S)
{
    extern __shared__ __align__(16) char sm[];
    __half* Vs = (__half*)sm;                        // [2][64][264]
    float*  Lf = (float*)(sm + 67584);               // [2][64][68]
    __half* Ps = (__half*)(sm + 67584 + 34816);      // [2][64][72]
    float*  Ls = (float*)(sm + 67584 + 34816 + 18432);
    const __half* V = g_svm_h;   // both recalls use speech_value_memory
    const int which = blockIdx.y;
    float* logits = which ? logits1 : logits0;
    float* outR   = which ? outR1   : outR0;
    const int lseoff = which ? N : 0;
    const int tid = threadIdx.x;
    const int warp = tid >> 5, lane = tid & 31;
    const int wm = warp >> 2, wn = warp & 3;
    const long bm = blockIdx.x;
    float* Lg = logits + bm * 64 * (long)S;
    uint32_t sv = (uint32_t)__cvta_generic_to_shared(Vs);
    uint32_t sl = (uint32_t)__cvta_generic_to_shared(Lf);

    if (tid < 64) {
        const float4* pp = reinterpret_cast<const float4*>(g_partial + (long)(lseoff + bm * 64 + tid) * 64);
        float s = 0.f;
        #pragma unroll
        for (int j = 0; j < 16; j++) { float4 v = pp[j]; s += v.x + v.y + v.z + v.w; }
        Ls[tid] = logf(s);
    }

    float acc[2][8][4] = {};

    // prologue loads stage 0
    #pragma unroll
    for (int i = 0; i < 8; i++) {
        int idx = tid + i * 256, r = idx >> 5, c = idx & 31;
        cpa16(sv + (unsigned)(r * 264 + c * 8) * 2, V + (long)r * 256 + c * 8);
    }
    #pragma unroll
    for (int i = 0; i < 4; i++) {
        int idx = tid + i * 256, r = idx >> 4, c = idx & 15;
        cpa16(sl + (unsigned)(r * 68 + c * 4) * 4, Lg + (long)r * S + c * 4);
    }
    CP_COMMIT;

    const int KB = S / 64;
    for (int kb = 0; kb < KB; ++kb) {
        CP_WAIT(0);
        __syncthreads();
        if (kb < KB - 1) {
            int st = (kb + 1) & 1;
            #pragma unroll
            for (int i = 0; i < 8; i++) {
                int idx = tid + i * 256, r = idx >> 5, c = idx & 31;
                cpa16(sv + (unsigned)(st * 16896 + r * 264 + c * 8) * 2,
                      V + (long)((kb + 1) * 64 + r) * 256 + c * 8);
            }
            #pragma unroll
            for (int i = 0; i < 4; i++) {
                int idx = tid + i * 256, r = idx >> 4, c = idx & 15;
                cpa16(sl + (unsigned)(st * 4352 + r * 68 + c * 4) * 4,
                      Lg + (long)r * S + (kb + 1) * 64 + c * 4);
            }
            CP_COMMIT;
        }
        const int st = kb & 1;
        // build Ps from Lf + writeback address_log
        #pragma unroll
        for (int i = 0; i < 4; i++) {
            int idx = tid + i * 256, r = idx >> 4, c = idx & 15;
            float4 v = *reinterpret_cast<float4*>(Lf + st * 4352 + r * 68 + c * 4);
            float l = Ls[r];
            v.x -= l; v.y -= l; v.z -= l; v.w -= l;
            *reinterpret_cast<float4*>(Lg + (long)r * S + kb * 64 + c * 4) = v;
            *reinterpret_cast<uint2*>(Ps + st * 4608 + r * 72 + c * 4) =
                make_uint2(pkh(__expf(v.x + PSHIFT), __expf(v.y + PSHIFT)),
                           pkh(__expf(v.z + PSHIFT), __expf(v.w + PSHIFT)));
        }
        __syncthreads();
        const __half* Pst = Ps + st * 4608;
        const __half* Vst = Vs + st * 16896;
        #pragma unroll
        for (int kk = 0; kk < 4; ++kk) {
            unsigned a[2][4], b[4][4];
            #pragma unroll
            for (int mt = 0; mt < 2; ++mt) {
                int r = wm * 32 + mt * 16 + (lane & 15);
                int c = kk * 16 + ((lane >> 4) << 3);
                ldsm4(a[mt], Pst + r * 72 + c);
            }
            #pragma unroll
            for (int np = 0; np < 4; ++np) {   // V rows=k, cols=n -> trans
                int g = lane >> 3;
                int r = kk * 16 + ((g & 1) << 3) + (lane & 7);
                int c = wn * 64 + np * 16 + ((g >> 1) << 3);
                ldsm4t(b[np], Vst + r * 264 + c);
            }
            #pragma unroll
            for (int mt = 0; mt < 2; ++mt)
                #pragma unroll
                for (int nt = 0; nt < 8; ++nt)
                    mma16816(acc[mt][nt], a[mt], b[nt >> 1][(nt & 1) * 2], b[nt >> 1][(nt & 1) * 2 + 1]);
        }
        __syncthreads();
    }

    #pragma unroll
    for (int mt = 0; mt < 2; ++mt) {
        int r = (int)(bm * 64) + wm * 32 + mt * 16 + (lane >> 2);
        #pragma unroll
        for (int nt = 0; nt < 8; ++nt) {
            int c = wn * 64 + nt * 8 + (lane & 3) * 2;
            *reinterpret_cast<float2*>(outR + (long)r * 256 + c) =
                make_float2(acc[mt][nt][0] * PSCALE, acc[mt][nt][1] * PSCALE);
            *reinterpret_cast<float2*>(outR + (long)(r + 8) * 256 + c) =
                make_float2(acc[mt][nt][2] * PSCALE, acc[mt][nt][3] * PSCALE);
        }
    }
}

// ---------------------------------------------------------------------------
static const int LOG_SMEM = 73728;
static const int REC_SMEM = 67584 + 34816 + 18432 + 256;

extern "C" void kernel_launch(void* const* d_in, const int* in_sizes, int n_in,
                              void* d_out, int out_size) {
    const float* face   = (const float*)d_in[0];
    const float* speech = (const float*)d_in[1];
    const float* svm    = (const float*)d_in[2];
    const float* fkm    = (const float*)d_in[3];
    const int C = 256;
    const int N = in_sizes[0] / C;   // 8192
    const int S = in_sizes[2] / C;   // 4096
    float* out = (float*)d_out;
    const long NC = (long)N * C;
    const long NS = (long)N * S;

    float* o_srec = out + NC;          // speech_emb_recall
    float* o_frec = out + 3 * NC;      // face_emb_recall
    float* o_slog = out + 4 * NC;      // speech_address_log (holds raw cos first)
    float* o_flog = out + 4 * NC + NS; // face_address_log

    cudaFuncSetAttribute(logits_kernel, cudaFuncAttributeMaxDynamicSharedMemorySize, LOG_SMEM);
    cudaFuncSetAttribute(recall_kernel, cudaFuncAttributeMaxDynamicSharedMemorySize, REC_SMEM);

    // identity embeddings
    cudaMemcpyAsync(out,          speech, NC * sizeof(float), cudaMemcpyDeviceToDevice, 0);
    cudaMemcpyAsync(out + 2 * NC, face,   NC * sizeof(float), cudaMemcpyDeviceToDevice, 0);

    int rows = 2 * N + 2 * S;
    convert_norms_kernel<<<(rows + 7) / 8, 256>>>(face, speech, svm, fkm, N, S);

    dim3 g2(S / 128, N / 128, 2);
    logits_kernel<<<g2, 256, LOG_SMEM>>>(o_slog, o_flog, N, S);

    dim3 g3(N / 64, 2);
    recall_kernel<<<g3, 256, REC_SMEM>>>(o_slog, o_flog, o_srec, o_frec, N, S);
}